// round 14
// baseline (speedup 1.0000x reference)
#include <cuda_runtime.h>

// MxAssemble: out[b,c,y,x] = sum_{dy,dx in [0,13)} aff[b, dy*13+dx, y, x] * in2zp[b, c, y+dy-6, x+dx-6]
// B=4, D=169, C=64, H=W=192, fp32.
// Pack-free f32x2 kernel: in2 tile stored TWICE in smem (copy B shifted by one
// float), so every f32x2 operand pair is an aligned LDS. 512-thread blocks,
// 64x x 8y x 16ch tile, CPT=4, 204.8KB dynamic smem (1 block/SM, 4 warps/SMSP).

#define BB   4
#define CC   64
#define HH   192
#define WW   192
#define WIN  13
#define DD   169
#define HWSZ (HH*WW)

#define TW    64     // x pixels per block
#define TH    8      // y rows per block
#define CBLK  16     // channels per block
#define CPT   4      // channels per thread
#define XR    4      // x pixels per thread
#define SROWS 20     // rows resident (8 + 12 halo)
#define SPITCH 80    // floats per smem row (320B)
#define PLANE (SROWS * SPITCH)          // 1600 floats per channel plane
#define ACOPY (CBLK * PLANE)            // 25600 floats per copy
#define SMEM_BYTES (2 * ACOPY * 4)      // 204800 B

typedef unsigned long long u64t;

__device__ __forceinline__ u64t ffma2(u64t a, u64t b, u64t c) {
    u64t d;
    asm("fma.rn.f32x2 %0, %1, %2, %3;" : "=l"(d) : "l"(a), "l"(b), "l"(c));
    return d;
}
__device__ __forceinline__ void unpackf2(u64t v, float& lo, float& hi) {
    asm("mov.b64 {%0, %1}, %2;" : "=f"(lo), "=f"(hi) : "l"(v));
}

union QU { ulonglong2 u; float4 f; };

__global__ __launch_bounds__(512, 1)
void mxassemble_kernel(const float* __restrict__ aff,
                       const float* __restrict__ in2,
                       float* __restrict__ out)
{
    extern __shared__ __align__(16) float smem[];
    float* sA = smem;           // aligned copy: col m <-> gx = x0-6+m
    float* sB = smem + ACOPY;   // shifted copy: sB[m] = value at gx = x0-6+m+1

    const int tx = threadIdx.x;      // 0..15  -> x group
    const int ty = threadIdx.y;      // 0..31
    const int yy = ty & 7;           // row within tile
    const int cq = ty >> 3;          // channel quarter (0..3)

    const int bx = blockIdx.x;       // 12 = 4 cgroups * 3 xtiles, cgroup fastest
    const int cg = bx & 3;
    const int xt = bx >> 2;
    const int yt = blockIdx.y;       // 0..23
    const int b  = blockIdx.z;       // 0..3

    const int x0 = xt * TW;
    const int y0 = yt * TH;
    const int c0 = cg * CBLK;

    const float* in2b = in2 + (size_t)b * CC * HWSZ;
    const int tid = ty * 16 + tx;    // 0..511

    // ---- cooperative fill of BOTH copies ---------------------------------
    // 6400 quads = 16 ch x 20 rows x 20 quads (gxq = x0-8+4q, q=0..19).
    {
        int q  = tid % 20;
        int rr = (tid / 20) % 20;
        int cc = tid / 400;
        #pragma unroll 1
        for (int it = 0; it < 13; it++) {
            if (it < 12 || tid < 256) {            // 12*512 + 256 = 6400
                const int gy  = y0 - 6 + rr;
                const int gxq = x0 - 8 + 4 * q;

                float4 v = make_float4(0.f, 0.f, 0.f, 0.f);
                if ((unsigned)gy < (unsigned)HH) {
                    const float* src = in2b + (size_t)(c0 + cc) * HWSZ + gy * WW + gxq;
                    if (gxq >= 0 && gxq <= WW - 4) {
                        v = *(const float4*)src;
                    } else {
                        if ((unsigned)(gxq + 0) < (unsigned)WW) v.x = src[0];
                        if ((unsigned)(gxq + 1) < (unsigned)WW) v.y = src[1];
                        if ((unsigned)(gxq + 2) < (unsigned)WW) v.z = src[2];
                        if ((unsigned)(gxq + 3) < (unsigned)WW) v.w = src[3];
                    }
                }
                const int c0q = 4 * q - 2;         // colA of v.x
                float* dA = sA + cc * PLANE + rr * SPITCH;
                float* dB = sB + cc * PLANE + rr * SPITCH;
                // copy A: cols c0q .. c0q+3
                if (c0q >= 0) *(float2*)(dA + c0q) = make_float2(v.x, v.y);
                *(float2*)(dA + c0q + 2) = make_float2(v.z, v.w);
                // copy B: B[m] = A[m+1]  -> cols c0q-1 .. c0q+2
                if (c0q > 0)  dB[c0q - 1] = v.x;
                if (c0q >= 0) *(float2*)(dB + c0q) = make_float2(v.y, v.z);
                dB[c0q + 2] = v.w;
            }
            // advance 512 quads = +12 q, +5 rows, +1 ch (with carries)
            q += 12;
            if (q >= 20) { q -= 20; rr += 1; }
            rr += 5;
            if (rr >= 20) { rr -= 20; cc += 1; }
            cc += 1;
        }
    }
    __syncthreads();

    // ---- main accumulation ------------------------------------------------
    u64t accA[CPT], accB[CPT];       // accA: outputs (xs, xs+1), accB: (xs+2, xs+3)
    #pragma unroll
    for (int c = 0; c < CPT; c++) { accA[c] = 0ull; accB[c] = 0ull; }

    const int xs = tx * XR;
    const float* affp = aff + (size_t)b * DD * HWSZ + (y0 + yy) * WW + x0 + xs;
    const float* sAc = sA + (cq * CPT) * PLANE + yy * SPITCH + xs;
    const float* sBc = sB + (cq * CPT) * PLANE + yy * SPITCH + xs;

    #pragma unroll 1
    for (int dy = 0; dy < WIN; dy++) {
        // aff operand pairs: ap[j].x = (a[j]@x0..x1), .y = (a[j]@x2..x3)
        ulonglong2 ap[WIN];
        #pragma unroll
        for (int j = 0; j < WIN; j++)
            ap[j] = *(const ulonglong2*)(affp + (size_t)(dy * WIN + j) * HWSZ);

        const int roff = dy * SPITCH;
        #pragma unroll
        for (int c = 0; c < CPT; c++) {
            const float* ra = sAc + c * PLANE + roff;
            const float* rb = sBc + c * PLANE + roff;
            QU a0, a1, a2, a3, b0, b1, b2, b3;
            a0.u = *(const ulonglong2*)(ra);
            a1.u = *(const ulonglong2*)(ra + 4);
            a2.u = *(const ulonglong2*)(ra + 8);
            a3.u = *(const ulonglong2*)(ra + 12);
            b0.u = *(const ulonglong2*)(rb);
            b1.u = *(const ulonglong2*)(rb + 4);
            b2.u = *(const ulonglong2*)(rb + 8);
            b3.u = *(const ulonglong2*)(rb + 12);

            // p[k] = (r[k], r[k+1]); even from A, odd from B — all register-direct
            u64t p[15];
            p[0]  = a0.u.x;  p[2]  = a0.u.y;  p[4]  = a1.u.x;  p[6]  = a1.u.y;
            p[8]  = a2.u.x;  p[10] = a2.u.y;  p[12] = a3.u.x;  p[14] = a3.u.y;
            p[1]  = b0.u.x;  p[3]  = b0.u.y;  p[5]  = b1.u.x;  p[7]  = b1.u.y;
            p[9]  = b2.u.x;  p[11] = b2.u.y;  p[13] = b3.u.x;

            #pragma unroll
            for (int j = 0; j < WIN; j++) {
                accA[c] = ffma2(ap[j].x, p[j],     accA[c]);
                accB[c] = ffma2(ap[j].y, p[j + 2], accB[c]);
            }
        }
    }

    // ---- write out --------------------------------------------------------
    float* outp = out + (size_t)b * CC * HWSZ + (y0 + yy) * WW + x0 + xs
                + (size_t)(c0 + cq * CPT) * HWSZ;
    #pragma unroll
    for (int c = 0; c < CPT; c++) {
        float4 v;
        unpackf2(accA[c], v.x, v.y);
        unpackf2(accB[c], v.z, v.w);
        *(float4*)(outp + (size_t)c * HWSZ) = v;
    }
}

extern "C" void kernel_launch(void* const* d_in, const int* in_sizes, int n_in,
                              void* d_out, int out_size)
{
    const float* aff = (const float*)d_in[0];   // [4,169,192,192]
    const float* in2 = (const float*)d_in[1];   // [4,64,192,192]
    float* out = (float*)d_out;                 // [4,64,192,192]

    static int smem_set = 0;
    if (!smem_set) {
        cudaFuncSetAttribute(mxassemble_kernel,
                             cudaFuncAttributeMaxDynamicSharedMemorySize,
                             SMEM_BYTES);
        smem_set = 1;
    }

    dim3 grid(12, 24, 4);   // (cgroup*xtile, ytile, batch) — cgroup fastest for aff L2 reuse
    dim3 block(16, 32);     // 512 threads
    mxassemble_kernel<<<grid, block, SMEM_BYTES>>>(aff, in2, out);
}

// round 15
// speedup vs baseline: 1.5126x; 1.5126x over previous
#include <cuda_runtime.h>

// MxAssemble: out[b,c,y,x] = sum_{dy,dx in [0,13)} aff[b, dy*13+dx, y, x] * in2zp[b, c, y+dy-6, x+dx-6]
// B=4, D=169, C=64, H=W=192, fp32.
// R6 tile (64x x 8y x 16ch, CPT=8, 102KB smem, 2 blocks/SM) with the dx loop
// chunked A(0-3)/B(4-7)/C(8-12) and the A-chunk aff operands double-buffered
// one dy ahead, so no exposed LDG latency at the dy heads.

#define BB   4
#define CC   64
#define HH   192
#define WW   192
#define WIN  13
#define DD   169
#define HWSZ (HH*WW)

#define TW    64     // x pixels per block
#define TH    8      // y rows per block
#define CBLK  16     // channels per block
#define CPT   8      // channels per thread
#define XR    4      // x pixels per thread
#define SROWS (TH+12)   // 20
#define SPITCH 80       // floats per smem row (320B, 16B aligned)
#define CSTRIDE (SROWS * SPITCH)

typedef unsigned long long u64t;

__device__ __forceinline__ u64t ffma2(u64t a, u64t b, u64t c) {
    u64t d;
    asm("fma.rn.f32x2 %0, %1, %2, %3;" : "=l"(d) : "l"(a), "l"(b), "l"(c));
    return d;
}
__device__ __forceinline__ u64t packf2(float lo, float hi) {
    u64t d;
    asm("mov.b64 %0, {%1, %2};" : "=l"(d) : "f"(lo), "f"(hi));
    return d;
}
__device__ __forceinline__ void unpackf2(u64t v, float& lo, float& hi) {
    asm("mov.b64 {%0, %1}, %2;" : "=f"(lo), "=f"(hi) : "l"(v));
}

union QU { ulonglong2 u; float4 f; };

__global__ __launch_bounds__(256, 2)
void mxassemble_kernel(const float* __restrict__ aff,
                       const float* __restrict__ in2,
                       float* __restrict__ out)
{
    __shared__ __align__(16) float s[CBLK][SROWS][SPITCH];   // 102,400 B

    const int tx = threadIdx.x;      // 0..15  -> x group
    const int ty = threadIdx.y;      // 0..15
    const int yy = ty & 7;           // row within tile
    const int ch = ty >> 3;          // channel half (0/1)

    const int bx = blockIdx.x;       // 12 = 4 cgroups * 3 xtiles, cgroup fastest
    const int cg = bx & 3;
    const int xt = bx >> 2;
    const int yt = blockIdx.y;       // 0..23
    const int b  = blockIdx.z;       // 0..3

    const int x0 = xt * TW;
    const int y0 = yt * TH;
    const int c0 = cg * CBLK;

    // ---- preload dy=0 chunk-A aff operands (independent of smem fill) -----
    const int xs = tx * XR;
    const float* affRow = aff + (size_t)b * DD * HWSZ + (y0 + yy) * WW + x0 + xs;

    ulonglong2 apA[4];
    #pragma unroll
    for (int j = 0; j < 4; j++)
        apA[j] = *(const ulonglong2*)(affRow + j * HWSZ);

    // ---- cooperative smem fill -------------------------------------------
    // 6400 quads = 16 planes x 20 rows x 20 aligned global quads (gxq = x0-8+4q).
    {
        const float* in2b = in2 + (size_t)b * CC * HWSZ;
        const int tid = ty * 16 + tx;
        int q  = tid % 20;
        int t2 = tid / 20;
        int rr = t2 % 20;
        int cc = t2 / 20;
        #pragma unroll 1
        for (int it = 0; it < 25; it++) {
            const int gy  = y0 - 6 + rr;
            const int gxq = x0 - 8 + 4 * q;

            float4 v = make_float4(0.f, 0.f, 0.f, 0.f);
            if ((unsigned)gy < (unsigned)HH) {
                const float* src = in2b + (size_t)(c0 + cc) * HWSZ + gy * WW + gxq;
                if (gxq >= 0 && gxq <= WW - 4) {
                    v = *(const float4*)src;
                } else {
                    if ((unsigned)(gxq + 0) < (unsigned)WW) v.x = src[0];
                    if ((unsigned)(gxq + 1) < (unsigned)WW) v.y = src[1];
                    if ((unsigned)(gxq + 2) < (unsigned)WW) v.z = src[2];
                    if ((unsigned)(gxq + 3) < (unsigned)WW) v.w = src[3];
                }
            }
            const int c0q = 4 * q - 2;               // smem col of v.x
            float* dst = &s[cc][rr][0];
            if (c0q >= 0) *(float2*)(dst + c0q) = make_float2(v.x, v.y);
            *(float2*)(dst + c0q + 2) = make_float2(v.z, v.w);

            // advance by 256 quads: 256 = 12*20 + 16
            q += 16; rr += 12;
            if (q >= 20)  { q -= 20; rr += 1; }
            if (rr >= 20) { rr -= 20; cc += 1; }
        }
    }
    __syncthreads();

    // ---- main accumulation ------------------------------------------------
    u64t accA[CPT], accB[CPT];       // accA: outputs (xs, xs+1), accB: (xs+2, xs+3)
    #pragma unroll
    for (int c = 0; c < CPT; c++) { accA[c] = 0ull; accB[c] = 0ull; }

    const float* sdy = &s[ch * CPT][0][0] + yy * SPITCH + xs;   // rolling smem base

    #pragma unroll 1
    for (int dy = 0; dy < WIN; dy++) {
        // issue B/C loads for this dy (consumed ~200/~400 slots later)
        ulonglong2 apB[4], apC[5];
        #pragma unroll
        for (int j = 0; j < 4; j++)
            apB[j] = *(const ulonglong2*)(affRow + (4 + j) * HWSZ);
        #pragma unroll
        for (int j = 0; j < 5; j++)
            apC[j] = *(const ulonglong2*)(affRow + (8 + j) * HWSZ);

        // ======== chunk A: j = 0..3 (cols xs..xs+6 -> Q0,Q1), apA ready ====
        #pragma unroll
        for (int c = 0; c < CPT; c++) {
            const float* sr = sdy + c * CSTRIDE;
            QU q0, q1;
            q0.u = *(const ulonglong2*)(sr);
            q1.u = *(const ulonglong2*)(sr + 4);
            const u64t p0 = q0.u.x, p2 = q0.u.y, p4 = q1.u.x;
            const u64t p1 = packf2(q0.f.y, q0.f.z);
            const u64t p3 = packf2(q0.f.w, q1.f.x);
            const u64t p5 = packf2(q1.f.y, q1.f.z);
            accA[c] = ffma2(apA[0].x, p0, accA[c]);  accB[c] = ffma2(apA[0].y, p2, accB[c]);
            accA[c] = ffma2(apA[1].x, p1, accA[c]);  accB[c] = ffma2(apA[1].y, p3, accB[c]);
            accA[c] = ffma2(apA[2].x, p2, accA[c]);  accB[c] = ffma2(apA[2].y, p4, accB[c]);
            accA[c] = ffma2(apA[3].x, p3, accA[c]);  accB[c] = ffma2(apA[3].y, p5, accB[c]);
        }

        // prefetch next dy's chunk-A operands (full B+C compute of cover)
        if (dy < WIN - 1) {
            const float* nextRow = affRow + WIN * HWSZ;
            #pragma unroll
            for (int j = 0; j < 4; j++)
                apA[j] = *(const ulonglong2*)(nextRow + j * HWSZ);
        }

        // ======== chunk B: j = 4..7 (cols xs+4..xs+10 -> Q1,Q2) ============
        #pragma unroll
        for (int c = 0; c < CPT; c++) {
            const float* sr = sdy + c * CSTRIDE;
            QU q1, q2;
            q1.u = *(const ulonglong2*)(sr + 4);
            q2.u = *(const ulonglong2*)(sr + 8);
            const u64t p4 = q1.u.x, p6 = q1.u.y, p8 = q2.u.x;
            const u64t p5 = packf2(q1.f.y, q1.f.z);
            const u64t p7 = packf2(q1.f.w, q2.f.x);
            const u64t p9 = packf2(q2.f.y, q2.f.z);
            accA[c] = ffma2(apB[0].x, p4, accA[c]);  accB[c] = ffma2(apB[0].y, p6, accB[c]);
            accA[c] = ffma2(apB[1].x, p5, accA[c]);  accB[c] = ffma2(apB[1].y, p7, accB[c]);
            accA[c] = ffma2(apB[2].x, p6, accA[c]);  accB[c] = ffma2(apB[2].y, p8, accB[c]);
            accA[c] = ffma2(apB[3].x, p7, accA[c]);  accB[c] = ffma2(apB[3].y, p9, accB[c]);
        }

        // ======== chunk C: j = 8..12 (cols xs+8..xs+15 -> Q2,Q3) ===========
        #pragma unroll
        for (int c = 0; c < CPT; c++) {
            const float* sr = sdy + c * CSTRIDE;
            QU q2, q3;
            q2.u = *(const ulonglong2*)(sr + 8);
            q3.u = *(const ulonglong2*)(sr + 12);
            const u64t p8 = q2.u.x, p10 = q2.u.y, p12 = q3.u.x, p14 = q3.u.y;
            const u64t p9  = packf2(q2.f.y, q2.f.z);
            const u64t p11 = packf2(q2.f.w, q3.f.x);
            const u64t p13 = packf2(q3.f.y, q3.f.z);
            accA[c] = ffma2(apC[0].x, p8,  accA[c]);  accB[c] = ffma2(apC[0].y, p10, accB[c]);
            accA[c] = ffma2(apC[1].x, p9,  accA[c]);  accB[c] = ffma2(apC[1].y, p11, accB[c]);
            accA[c] = ffma2(apC[2].x, p10, accA[c]);  accB[c] = ffma2(apC[2].y, p12, accB[c]);
            accA[c] = ffma2(apC[3].x, p11, accA[c]);  accB[c] = ffma2(apC[3].y, p13, accB[c]);
            accA[c] = ffma2(apC[4].x, p12, accA[c]);  accB[c] = ffma2(apC[4].y, p14, accB[c]);
        }

        affRow += WIN * HWSZ;
        sdy    += SPITCH;
    }

    // ---- write out --------------------------------------------------------
    float* outp = out + (size_t)b * CC * HWSZ + (y0 + yy) * WW + x0 + xs
                + (size_t)(c0 + ch * CPT) * HWSZ;
    #pragma unroll
    for (int c = 0; c < CPT; c++) {
        float4 v;
        unpackf2(accA[c], v.x, v.y);
        unpackf2(accB[c], v.z, v.w);
        *(float4*)(outp + (size_t)c * HWSZ) = v;
    }
}

extern "C" void kernel_launch(void* const* d_in, const int* in_sizes, int n_in,
                              void* d_out, int out_size)
{
    const float* aff = (const float*)d_in[0];   // [4,169,192,192]
    const float* in2 = (const float*)d_in[1];   // [4,64,192,192]
    float* out = (float*)d_out;                 // [4,64,192,192]

    dim3 grid(12, 24, 4);   // (cgroup*xtile, ytile, batch) — cgroup fastest for aff L2 reuse
    dim3 block(16, 16);
    mxassemble_kernel<<<grid, block>>>(aff, in2, out);
}